// round 2
// baseline (speedup 1.0000x reference)
#include <cuda_runtime.h>
#include <cstdint>

#define NN 50000
#define KD 512
#define EM 128
#define OD 64

// ---------------- scratch (device globals: no allocation allowed) ----------------
__device__ float g_h[(size_t)NN * EM];   // hidden after dense+lrelu
__device__ float g_g[(size_t)NN * OD];   // g = h @ Wg^T
__device__ float g_as[NN];               // a_src per node
__device__ float g_ad[NN];               // a_dst per node
__device__ float g_m[NN];                // segment max
__device__ float g_den[NN];              // segment sum of exp

// ---------------- init: m=-inf, den=0, out=0 ----------------
__global__ void k_init(float* __restrict__ out) {
    int i = blockIdx.x * blockDim.x + threadIdx.x;
    if (i < NN) {
        g_m[i]   = __int_as_float(0xff800000); // -inf
        g_den[i] = 0.f;
    }
    if (i < NN * OD) out[i] = 0.f;
}

// ---------------- GEMM1: H = lrelu(X @ Wd^T + bd, 0.01) ----------------
// X[NN,512] row-major, Wd[128,512] row-major. Tile 64 rows x 128 cols, K-chunk 32.
#define BM 64
#define BN 128
#define BK 32
__global__ __launch_bounds__(256) void k_gemm1(const float* __restrict__ X,
                                               const float* __restrict__ Wd,
                                               const float* __restrict__ bd) {
    __shared__ float As[BK][BM + 4];   // As[k][row]
    __shared__ float Bs[BK][BN + 4];   // Bs[k][col]
    const int tid = threadIdx.x;
    const int tx = tid & 15;           // col group 0..15  -> cols tx*8 .. tx*8+7
    const int ty = tid >> 4;           // row group 0..15  -> rows ty*4 .. ty*4+3
    const int row0 = blockIdx.x * BM;

    float acc[4][8];
#pragma unroll
    for (int i = 0; i < 4; i++)
#pragma unroll
        for (int j = 0; j < 8; j++) acc[i][j] = 0.f;

    for (int k0 = 0; k0 < KD; k0 += BK) {
        // A tile: 64 rows x 32 k = 512 float4, 2 per thread (transposed store)
#pragma unroll
        for (int i = 0; i < 2; i++) {
            int f = tid + i * 256;       // 0..511
            int r = f >> 3;              // 0..63
            int kq = f & 7;              // float4 id
            float4 v = make_float4(0.f, 0.f, 0.f, 0.f);
            int rg = row0 + r;
            if (rg < NN)
                v = *reinterpret_cast<const float4*>(X + (size_t)rg * KD + k0 + kq * 4);
            As[kq * 4 + 0][r] = v.x; As[kq * 4 + 1][r] = v.y;
            As[kq * 4 + 2][r] = v.z; As[kq * 4 + 3][r] = v.w;
        }
        // B tile: 128 cols x 32 k = 1024 float4, 4 per thread (transposed store)
#pragma unroll
        for (int i = 0; i < 4; i++) {
            int f = tid + i * 256;       // 0..1023
            int c = f >> 3;              // 0..127
            int kq = f & 7;
            float4 v = *reinterpret_cast<const float4*>(Wd + (size_t)c * KD + k0 + kq * 4);
            Bs[kq * 4 + 0][c] = v.x; Bs[kq * 4 + 1][c] = v.y;
            Bs[kq * 4 + 2][c] = v.z; Bs[kq * 4 + 3][c] = v.w;
        }
        __syncthreads();
#pragma unroll
        for (int kk = 0; kk < BK; kk++) {
            float4 a  = *reinterpret_cast<const float4*>(&As[kk][ty * 4]);
            float4 b0 = *reinterpret_cast<const float4*>(&Bs[kk][tx * 8]);
            float4 b1 = *reinterpret_cast<const float4*>(&Bs[kk][tx * 8 + 4]);
            float av[4] = {a.x, a.y, a.z, a.w};
            float bv[8] = {b0.x, b0.y, b0.z, b0.w, b1.x, b1.y, b1.z, b1.w};
#pragma unroll
            for (int i = 0; i < 4; i++)
#pragma unroll
                for (int j = 0; j < 8; j++) acc[i][j] = fmaf(av[i], bv[j], acc[i][j]);
        }
        __syncthreads();
    }
    // epilogue: + bias, leaky relu 0.01, store H
#pragma unroll
    for (int i = 0; i < 4; i++) {
        int r = row0 + ty * 4 + i;
        if (r >= NN) continue;
#pragma unroll
        for (int j = 0; j < 8; j++) {
            int c = tx * 8 + j;
            float v = acc[i][j] + __ldg(bd + c);
            v = v > 0.f ? v : 0.01f * v;
            g_h[(size_t)r * EM + c] = v;
        }
    }
}

// ---------------- GEMM2 + attention logits ----------------
// G = H @ Wg^T (Wg[64,128]); a_src = G @ att_src; a_dst = G @ att_dst
#define RPB 128   // rows per block
__global__ __launch_bounds__(256) void k_gemm2(const float* __restrict__ Wg,
                                               const float* __restrict__ att_s,
                                               const float* __restrict__ att_d) {
    __shared__ float Wgs[OD][EM + 4];   // [col][k], padded for conflict-free float4 reads
    __shared__ float hs[4][EM];
    __shared__ float red_s[4][2], red_d[4][2];
    __shared__ float ats[OD], atd[OD];
    const int tid = threadIdx.x;
    const int tx = tid & 63;           // output col
    const int ty = tid >> 6;           // row within 4-row group

    // load Wg: 8192 floats = 2048 float4, 8 per thread
#pragma unroll
    for (int i = 0; i < 8; i++) {
        int f = tid + i * 256;
        int c = f >> 5;      // 0..63
        int kq = f & 31;     // 0..31
        float4 v = *reinterpret_cast<const float4*>(Wg + (size_t)c * EM + kq * 4);
        *reinterpret_cast<float4*>(&Wgs[c][kq * 4]) = v;
    }
    if (tid < OD) { ats[tid] = att_s[tid]; atd[tid] = att_d[tid]; }

    const int base = blockIdx.x * RPB;
    for (int rg = 0; rg < RPB; rg += 4) {
        __syncthreads();   // Wgs ready (1st iter) / hs+red consumed (later iters)
        if (tid < 128) {
            int r = tid >> 5;
            int kq = tid & 31;
            int row = base + rg + r;
            float4 v = make_float4(0.f, 0.f, 0.f, 0.f);
            if (row < NN)
                v = *reinterpret_cast<const float4*>(g_h + (size_t)row * EM + kq * 4);
            *reinterpret_cast<float4*>(&hs[r][kq * 4]) = v;
        }
        __syncthreads();
        int row = base + rg + ty;
        float acc = 0.f;
#pragma unroll
        for (int k = 0; k < EM; k += 4) {
            float4 w  = *reinterpret_cast<const float4*>(&Wgs[tx][k]);
            float4 h4 = *reinterpret_cast<const float4*>(&hs[ty][k]);
            acc = fmaf(w.x, h4.x, acc);
            acc = fmaf(w.y, h4.y, acc);
            acc = fmaf(w.z, h4.z, acc);
            acc = fmaf(w.w, h4.w, acc);
        }
        if (row < NN) g_g[(size_t)row * OD + tx] = acc;

        float ps = acc * ats[tx];
        float pd = acc * atd[tx];
#pragma unroll
        for (int off = 16; off > 0; off >>= 1) {
            ps += __shfl_xor_sync(0xffffffffu, ps, off);
            pd += __shfl_xor_sync(0xffffffffu, pd, off);
        }
        int half = tx >> 5;
        if ((tx & 31) == 0) { red_s[ty][half] = ps; red_d[ty][half] = pd; }
        __syncthreads();
        if (tx == 0 && row < NN) {
            g_as[row] = red_s[ty][0] + red_s[ty][1];
            g_ad[row] = red_d[ty][0] + red_d[ty][1];
        }
    }
}

// ---------------- edge pass 1: segment max over dst ----------------
__global__ void k_edge_max(const int* __restrict__ ei, int E) {
    int i = blockIdx.x * blockDim.x + threadIdx.x;
    int total = E + NN;
    if (i >= total) return;
    int s, d;
    if (i < E) { s = ei[i]; d = ei[E + i]; }
    else       { s = d = i - E; }            // self loop
    float e = g_as[s] + g_ad[d];
    e = e > 0.f ? e : 0.2f * e;
    // sign-routed float atomic max (handles -0.0 correctly)
    if ((__float_as_uint(e) >> 31) == 0)
        atomicMax(reinterpret_cast<int*>(g_m + d), __float_as_int(e));
    else
        atomicMin(reinterpret_cast<unsigned int*>(g_m + d), __float_as_uint(e));
}

// ---------------- edge pass 2: exp weight, denom, weighted scatter of g[src] ----------------
// 16 threads per edge: one float4 gather + one red.global.add.v4.f32 each.
__global__ void k_edge_acc(const int* __restrict__ ei, int E, float* __restrict__ out) {
    int gid = blockIdx.x * blockDim.x + threadIdx.x;
    int edge = gid >> 4;
    int lane = gid & 15;
    int total = E + NN;
    if (edge >= total) return;
    int s, d;
    if (edge < E) { s = ei[edge]; d = ei[E + edge]; }
    else          { s = d = edge - E; }
    float e = g_as[s] + g_ad[d];
    e = e > 0.f ? e : 0.2f * e;
    float w = __expf(e - g_m[d]);
    if (lane == 0) atomicAdd(g_den + d, w);
    float4 v = *reinterpret_cast<const float4*>(g_g + (size_t)s * OD + lane * 4);
    v.x *= w; v.y *= w; v.z *= w; v.w *= w;
    float* p = out + (size_t)d * OD + lane * 4;
    asm volatile("red.global.add.v4.f32 [%0], {%1,%2,%3,%4};"
                 :: "l"(p), "f"(v.x), "f"(v.y), "f"(v.z), "f"(v.w)
                 : "memory");
}

// ---------------- finalize: normalize + bias ----------------
__global__ void k_final(float* __restrict__ out, const float* __restrict__ bg) {
    int i = blockIdx.x * blockDim.x + threadIdx.x;
    if (i >= NN * OD) return;
    int d = i >> 6;
    int c = i & 63;
    out[i] = out[i] / g_den[d] + __ldg(bg + c);
}

// ---------------- launch ----------------
extern "C" void kernel_launch(void* const* d_in, const int* in_sizes, int n_in,
                              void* d_out, int out_size) {
    const float* x   = (const float*)d_in[0];
    const int*   ei  = (const int*)  d_in[1];
    const float* Wd  = (const float*)d_in[2];
    const float* bd  = (const float*)d_in[3];
    const float* Wg  = (const float*)d_in[4];
    const float* ats = (const float*)d_in[5];
    const float* atd = (const float*)d_in[6];
    const float* bg  = (const float*)d_in[7];
    float* out = (float*)d_out;

    const int E = in_sizes[1] / 2;
    const int total = E + NN;

    k_init<<<(NN * OD + 255) / 256, 256>>>(out);
    k_gemm1<<<(NN + BM - 1) / BM, 256>>>(x, Wd, bd);
    k_gemm2<<<(NN + RPB - 1) / RPB, 256>>>(Wg, ats, atd);
    k_edge_max<<<(total + 255) / 256, 256>>>(ei, E);
    {
        long long threads = (long long)total * 16;
        int blocks = (int)((threads + 255) / 256);
        k_edge_acc<<<blocks, 256>>>(ei, E, out);
    }
    k_final<<<(NN * OD + 255) / 256, 256>>>(out, bg);
}